// round 8
// baseline (speedup 1.0000x reference)
#include <cuda_runtime.h>
#include <cuda_bf16.h>

// Problem constants (match reference)
#define N_CLASSES   4
#define TIME_STEPS  120
#define BATCH       65536
#define NTHREADS    (BATCH * N_CLASSES)   // 262144: one thread per (batch, class)
#define DT_MS       10.0f
#define THRESH      0.5f
#define EPS_F       1e-9f
#define L2E_F       1.4426950408889634f   // log2(e)
#define LN2_F       0.6931471805599453f

__device__ __forceinline__ float fast_softplus(float x) {
    // parameter transform only (not in hot loop)
    float e = __expf(-fabsf(x));
    return fmaxf(x, 0.0f) + __logf(1.0f + e);
}

// One thread per (batch, class). Threads 4b..4b+3 (one lane quad) hold the 4
// classes of batch element b. Quad sum uses 3 INDEPENDENT shfl_xor ops
// (parallel, ~34-cycle chain) instead of a serial butterfly (~60 cycles).
// Drive coefficients are prescaled by log2(e): softplus runs natively in
// base 2; with |drive| bounded O(5) by the contractive dynamics, the
// unstable form log2(1+exp2(x)) is exact to fp32 here and saves the
// abs/max range split.
__global__ __launch_bounds__(256)
void acc_race_kernel(const float* __restrict__ logits,      // [B*4]
                     const float* __restrict__ p_iscale,
                     const float* __restrict__ p_leak,      // [4]
                     const float* __restrict__ p_se,        // [4]
                     const float* __restrict__ p_inh,
                     const float* __restrict__ p_ns,
                     const float* __restrict__ p_w,         // [1,1]
                     const float* __restrict__ p_b,         // [1]
                     const float* __restrict__ noise,       // [T*B*4]
                     float*       __restrict__ out)         // [B*4]
{
    const int tid = blockIdx.x * blockDim.x + threadIdx.x;
    const int c   = tid & (N_CLASSES - 1);

    // ---- parameters (broadcast loads; transform once) ----
    const float iscale = *p_iscale;
    const float w      = *p_w;
    const float bias   = *p_b;
    const float inh    = fast_softplus(*p_inh);
    const float ns     = fast_softplus(*p_ns);
    const float coefp = (fast_softplus(p_se[c]) + inh - fast_softplus(p_leak[c])) * L2E_F;
    const float inhp  = inh * L2E_F;
    const float nsp   = ns  * L2E_F;
    const float evp   = fmaf(fmaxf(logits[tid] * iscale, 0.0f), w, bias) * L2E_F;
    const float K     = 0.2f * LN2_F;   // Euler step absorbs base-2 scale

    // ---- rollout state ----
    float acc = 0.0f;
    float cp = 0.0f, cc = 0.0f, tc = 0.0f;  // crossPrev/crossCur (raw acc), step count
    bool  cr = false;

    const float* np = noise + tid;
    float nz = *np;

#define STEP_BODY                                                             \
    do {                                                                      \
        /* acc-independent part first: overlaps with the shuffles */          \
        const float evn = fmaf(nsp, nz, evp);                                 \
        const float t1 = __shfl_xor_sync(0xffffffffu, acc, 1);                \
        const float t2 = __shfl_xor_sync(0xffffffffu, acc, 2);                \
        const float t3 = __shfl_xor_sync(0xffffffffu, acc, 3);                \
        const float x  = fmaf(coefp, acc, evn);                               \
        const float total = (acc + t1) + (t2 + t3);                           \
        const float dp = fmaf(-inhp, total, x);                               \
        const float sb = __log2f(1.0f + exp2f(dp));                           \
        acc = fmaxf(fmaf(K, sb, 0.8f * acc), 0.0f);                           \
        /* crossing bookkeeping: overwrite until crossed, then freeze */      \
        const bool nc = !cr;                                                  \
        cp = nc ? cc : cp;                                                    \
        cc = nc ? acc : cc;                                                   \
        tc = nc ? tc + 1.0f : tc;                                             \
        cr = cr || (acc >= THRESH);                                           \
    } while (0)

    // 119 prefetching iterations (119 = 7*17, unrolls evenly) + 1 peeled tail
#pragma unroll 7
    for (int t = 0; t < TIME_STEPS - 1; ++t) {
        np += NTHREADS;
        const float nz_next = *np;
        STEP_BODY;
        nz = nz_next;
    }
    STEP_BODY;   // t = 119, no prefetch
#undef STEP_BODY

    // ---- epilogue: interpolate first-crossing time ----
    // prev = cp - THRESH, cur = cc - THRESH; THRESH cancels in denominator.
    float tm;
    if (cr) {
        const float idx = tc - 1.0f;    // first crossing index (float)
        tm = (idx > 0.0f)
               ? (idx - 1.0f + (THRESH - cp) / (cc - cp + EPS_F)) * DT_MS
               : 0.0f;                  // crossed at idx 0
    } else {
        tm = (float)TIME_STEPS * DT_MS; // never crossed: 1200 ms
    }
    out[tid] = tm * 0.001f;             // -> seconds
}

extern "C" void kernel_launch(void* const* d_in, const int* in_sizes, int n_in,
                              void* d_out, int out_size)
{
    const float* logits = (const float*)d_in[0];
    const float* iscale = (const float*)d_in[1];
    const float* leak   = (const float*)d_in[2];
    const float* se     = (const float*)d_in[3];
    const float* inh    = (const float*)d_in[4];
    const float* ns     = (const float*)d_in[5];
    const float* pw     = (const float*)d_in[6];
    const float* pb     = (const float*)d_in[7];
    const float* noise  = (const float*)d_in[8];
    float*       out    = (float*)d_out;

    const int threads = 256;
    const int blocks  = NTHREADS / threads;   // 1024
    acc_race_kernel<<<blocks, threads>>>(logits, iscale, leak, se, inh, ns,
                                         pw, pb, noise, out);
}